// round 5
// baseline (speedup 1.0000x reference)
#include <cuda_runtime.h>
#include <math.h>

#define B_   2
#define S_   2048
#define H_   2048
#define NH_  16
#define D_   128
#define LAT_ 512
#define MS_  (B_*S_)   // 4096 rows total

// ---------------- scratch (device globals; no allocation allowed) ----------
__device__ float g_ckv[MS_*LAT_];
__device__ float g_cq [MS_*LAT_];
__device__ float g_kc [MS_*H_];
__device__ float g_vc [MS_*H_];
__device__ float g_qc [MS_*H_];
__device__ float g_kr [MS_*D_];
__device__ float g_qr [MS_*D_];
__device__ float g_ctx[MS_*H_];

// ---------------- fp32 tiled GEMM: C = A(MxK) @ B(KxN) + bias --------------
// BM=128, BN=64, BK=16, 256 threads, 8x4 micro-tile per thread.
__global__ __launch_bounds__(256) void sgemm_bias(
    const float* __restrict__ A, const float* __restrict__ Bm,
    const float* __restrict__ bias, float* __restrict__ C,
    int M, int N, int K)
{
    __shared__ float As[16][128];
    __shared__ float Bs[16][64];
    const int tid  = threadIdx.x;
    const int ty   = tid >> 4;        // 0..15 -> 8 C-rows each
    const int tx   = tid & 15;        // 0..15 -> 4 C-cols each
    const int row0 = blockIdx.y * 128;
    const int col0 = blockIdx.x * 64;

    float acc[8][4];
#pragma unroll
    for (int i = 0; i < 8; i++)
#pragma unroll
        for (int j = 0; j < 4; j++) acc[i][j] = 0.f;

    const int ar  = tid >> 1;         // 0..127 : A-tile row
    const int ac4 = (tid & 1) * 2;    // float4 chunk base (0 or 2)
    const int br  = tid >> 4;         // 0..15  : B-tile row
    const int bc4 = tid & 15;         // float4 chunk

    for (int k0 = 0; k0 < K; k0 += 16) {
        // A tile 128x16: 2 float4 per thread, stored transposed As[k][m]
#pragma unroll
        for (int t = 0; t < 2; t++) {
            float4 v = *(const float4*)&A[(row0 + ar) * K + k0 + (ac4 + t) * 4];
            int c = (ac4 + t) * 4;
            As[c + 0][ar] = v.x; As[c + 1][ar] = v.y;
            As[c + 2][ar] = v.z; As[c + 3][ar] = v.w;
        }
        // B tile 16x64: 1 float4 per thread
        {
            float4 v = *(const float4*)&Bm[(k0 + br) * N + col0 + bc4 * 4];
            *(float4*)&Bs[br][bc4 * 4] = v;
        }
        __syncthreads();
#pragma unroll
        for (int k = 0; k < 16; k++) {
            float a[8], b[4];
            *(float4*)&a[0] = *(const float4*)&As[k][ty * 8];
            *(float4*)&a[4] = *(const float4*)&As[k][ty * 8 + 4];
            *(float4*)&b[0] = *(const float4*)&Bs[k][tx * 4];
#pragma unroll
            for (int i = 0; i < 8; i++)
#pragma unroll
                for (int j = 0; j < 4; j++) acc[i][j] += a[i] * b[j];
        }
        __syncthreads();
    }
    float4 bv = *(const float4*)&bias[col0 + tx * 4];
#pragma unroll
    for (int i = 0; i < 8; i++) {
        float4 o;
        o.x = acc[i][0] + bv.x; o.y = acc[i][1] + bv.y;
        o.z = acc[i][2] + bv.z; o.w = acc[i][3] + bv.w;
        *(float4*)&C[(row0 + ty * 8 + i) * N + col0 + tx * 4] = o;
    }
}

// ---------------- rope (in place, one row per block, 128 threads) ----------
__global__ void rope_kernel(float* __restrict__ x)
{
    int row = blockIdx.x;
    int d   = threadIdx.x;       // 0..127
    __shared__ float buf[128];
    buf[d] = x[row * D_ + d];
    __syncthreads();
    int i = d & 63;
    // inv_freq = 10000^(-2i/128); double->float gives correctly-rounded value
    float inv = (float)exp(-(double)(2 * i) / 128.0 * 9.210340371976184);
    float ang = (float)(row & (S_ - 1)) * inv;   // pos = row % S
    float s, c;
    sincosf(ang, &s, &c);
    float y = (d < 64) ? (buf[d] * c - buf[d + 64] * s)
                       : (buf[d - 64] * s + buf[d] * c);
    x[row * D_ + d] = y;
}

// ---------------- flash attention (fp32) -----------------------------------
// grid (S/64, NH, B), 256 threads. 4 threads per query row; effective QK dim
// 256 = [k_c | rope(k_r)]. 32-key tiles in smem (exactly 48KB static).
// Swizzled float4 chunk indices keep all LDS.128 bank-conflict-free.
__global__ __launch_bounds__(256, 1) void mla_attn_kernel(
    const float* __restrict__ qc, const float* __restrict__ qr,
    const float* __restrict__ kc, const float* __restrict__ kr,
    const float* __restrict__ vc, const int* __restrict__ mask,
    float* __restrict__ ctx)
{
    __shared__ float Ks[32 * 256];  // [j][0:256] = [k_c | k_r]
    __shared__ float Vs[32 * 128];

    const int tid = threadIdx.x;
    const int r   = tid >> 2;       // query row within tile (0..63)
    const int q4  = tid & 3;        // quarter of the 256-dim dot
    const int b   = blockIdx.z, h = blockIdx.y;
    const int sq  = blockIdx.x * 64 + r;
    const int rowq = b * S_ + sq;

    // Load this thread's 64 Q dims (16 float4, swizzled chunk order)
    float4 qv[16];
#pragma unroll
    for (int d4 = 0; d4 < 16; d4++) {
        int chunk = q4 * 16 + ((d4 + 2 * q4) & 15);
        int dim   = chunk * 4;
        const float* src = (dim < 128)
            ? &qc[rowq * H_ + h * D_ + dim]
            : &qr[rowq * D_ + (dim - 128)];
        qv[d4] = *(const float4*)src;
    }

    float m = -1e30f, l = 0.f;
    float4 o[8];
#pragma unroll
    for (int i = 0; i < 8; i++) o[i] = make_float4(0.f, 0.f, 0.f, 0.f);

    const float scale = 0.08838834764831845f;   // 1/sqrt(128)

    for (int kt = 0; kt < S_ / 32; kt++) {
        const int s0 = kt * 32;
        __syncthreads();
        // K tile: 32 rows x 64 chunks -> 8 float4 per thread
#pragma unroll
        for (int t = 0; t < 8; t++) {
            int idx = tid + t * 256;        // 0..2047
            int j   = idx >> 6;
            int dim = (idx & 63) * 4;
            int rowk = b * S_ + s0 + j;
            float4 v = (dim < 128)
                ? *(const float4*)&kc[rowk * H_ + h * D_ + dim]
                : *(const float4*)&kr[rowk * D_ + (dim - 128)];
            *(float4*)&Ks[j * 256 + dim] = v;
        }
        // V tile: 32 rows x 32 chunks -> 4 float4 per thread
#pragma unroll
        for (int t = 0; t < 4; t++) {
            int idx = tid + t * 256;
            int j   = idx >> 5;
            int dim = (idx & 31) * 4;
            int rowk = b * S_ + s0 + j;
            *(float4*)&Vs[j * 128 + dim] =
                *(const float4*)&vc[rowk * H_ + h * D_ + dim];
        }
        __syncthreads();

        // scores for 32 keys
        float sc[32];
#pragma unroll
        for (int j = 0; j < 32; j++) {
            float4 a = make_float4(0.f, 0.f, 0.f, 0.f);
#pragma unroll
            for (int d4 = 0; d4 < 16; d4++) {
                int chunk = q4 * 16 + ((d4 + 2 * q4) & 15);
                float4 kv = *(const float4*)&Ks[j * 256 + chunk * 4];
                a.x += qv[d4].x * kv.x; a.y += qv[d4].y * kv.y;
                a.z += qv[d4].z * kv.z; a.w += qv[d4].w * kv.w;
            }
            float s = (a.x + a.y) + (a.z + a.w);
            s += __shfl_xor_sync(0xffffffffu, s, 1);
            s += __shfl_xor_sync(0xffffffffu, s, 2);
            s *= scale;
            if (mask[b * S_ + s0 + j] == 0) s = -1e30f;
            sc[j] = s;
        }

        float tmax = sc[0];
#pragma unroll
        for (int j = 1; j < 32; j++) tmax = fmaxf(tmax, sc[j]);
        float mnew = fmaxf(m, tmax);
        float corr = __expf(m - mnew);
        l *= corr;
#pragma unroll
        for (int i = 0; i < 8; i++) {
            o[i].x *= corr; o[i].y *= corr; o[i].z *= corr; o[i].w *= corr;
        }
#pragma unroll
        for (int j = 0; j < 32; j++) {
            float p = __expf(sc[j] - mnew);
            l += p;
#pragma unroll
            for (int i4 = 0; i4 < 8; i4++) {
                int chunk = q4 * 8 + ((i4 + 2 * q4) & 7);
                float4 v = *(const float4*)&Vs[j * 128 + chunk * 4];
                o[i4].x += p * v.x; o[i4].y += p * v.y;
                o[i4].z += p * v.z; o[i4].w += p * v.w;
            }
        }
        m = mnew;
    }

    float inv_l = 1.0f / l;
#pragma unroll
    for (int i4 = 0; i4 < 8; i4++) {
        int chunk = q4 * 8 + ((i4 + 2 * q4) & 7);
        float4 ov = o[i4];
        ov.x *= inv_l; ov.y *= inv_l; ov.z *= inv_l; ov.w *= inv_l;
        *(float4*)&ctx[rowq * H_ + h * D_ + chunk * 4] = ov;
    }
}

// ---------------- launch ----------------------------------------------------
extern "C" void kernel_launch(void* const* d_in, const int* in_sizes, int n_in,
                              void* d_out, int out_size)
{
    const float* hs    = (const float*)d_in[0];
    const int*   mask  = (const int*)  d_in[1];
    const float* W_DKV = (const float*)d_in[2];  const float* b_DKV = (const float*)d_in[3];
    const float* W_DQ  = (const float*)d_in[4];  const float* b_DQ  = (const float*)d_in[5];
    const float* W_UK  = (const float*)d_in[6];  const float* b_UK  = (const float*)d_in[7];
    const float* W_UV  = (const float*)d_in[8];  const float* b_UV  = (const float*)d_in[9];
    const float* W_UQ  = (const float*)d_in[10]; const float* b_UQ  = (const float*)d_in[11];
    const float* W_KR  = (const float*)d_in[12]; const float* b_KR  = (const float*)d_in[13];
    const float* W_QR  = (const float*)d_in[14]; const float* b_QR  = (const float*)d_in[15];
    const float* W_O   = (const float*)d_in[16]; const float* b_O   = (const float*)d_in[17];
    float* out = (float*)d_out;

    float *ckv, *cq, *kc, *vc, *qc, *kr, *qr, *ctx;
    cudaGetSymbolAddress((void**)&ckv, g_ckv);
    cudaGetSymbolAddress((void**)&cq,  g_cq);
    cudaGetSymbolAddress((void**)&kc,  g_kc);
    cudaGetSymbolAddress((void**)&vc,  g_vc);
    cudaGetSymbolAddress((void**)&qc,  g_qc);
    cudaGetSymbolAddress((void**)&kr,  g_kr);
    cudaGetSymbolAddress((void**)&qr,  g_qr);
    cudaGetSymbolAddress((void**)&ctx, g_ctx);

    const dim3 blk(256);

    // down-projections + rope projections
    sgemm_bias<<<dim3(LAT_/64, MS_/128), blk>>>(hs, W_DKV, b_DKV, ckv, MS_, LAT_, H_);
    sgemm_bias<<<dim3(LAT_/64, MS_/128), blk>>>(hs, W_DQ,  b_DQ,  cq,  MS_, LAT_, H_);
    sgemm_bias<<<dim3(D_/64,   MS_/128), blk>>>(hs, W_KR,  b_KR,  kr,  MS_, D_,   H_);
    sgemm_bias<<<dim3(D_/64,   MS_/128), blk>>>(hs, W_QR,  b_QR,  qr,  MS_, D_,   H_);
    rope_kernel<<<MS_, 128>>>(kr);
    rope_kernel<<<MS_, 128>>>(qr);

    // up-projections
    sgemm_bias<<<dim3(H_/64, MS_/128), blk>>>(ckv, W_UK, b_UK, kc, MS_, H_, LAT_);
    sgemm_bias<<<dim3(H_/64, MS_/128), blk>>>(ckv, W_UV, b_UV, vc, MS_, H_, LAT_);
    sgemm_bias<<<dim3(H_/64, MS_/128), blk>>>(cq,  W_UQ, b_UQ, qc, MS_, H_, LAT_);

    // attention
    mla_attn_kernel<<<dim3(S_/64, NH_, B_), 256>>>(qc, qr, kc, kr, vc, mask, ctx);

    // output projection
    sgemm_bias<<<dim3(H_/64, MS_/128), blk>>>(ctx, W_O, b_O, out, MS_, H_, H_);
}

// round 6
// speedup vs baseline: 1.1028x; 1.1028x over previous
#include <cuda_runtime.h>
#include <cuda_bf16.h>
#include <math.h>

#define B_   2
#define S_   2048
#define H_   2048
#define NH_  16
#define D_   128
#define LAT_ 512
#define MS_  (B_*S_)   // 4096 rows total

// ---------------- scratch (device globals; no allocation allowed) ----------
__device__ float g_ckv[MS_*LAT_];
__device__ float g_cq [MS_*LAT_];
__device__ float g_kc [MS_*H_];
__device__ float g_vc [MS_*H_];
__device__ float g_qc [MS_*H_];
__device__ float g_kr [MS_*D_];
__device__ float g_qr [MS_*D_];
__device__ float g_ctx[MS_*H_];

// pre-split / transposed bf16 weights ([N][K] layout), hi + lo residual
#define OFF_DKV 0
#define OFF_DQ  1048576
#define OFF_UK  2097152
#define OFF_UV  3145728
#define OFF_UQ  4194304
#define OFF_O   5242880
#define WTOT    9437184
__device__ __nv_bfloat16 g_whi[WTOT];
__device__ __nv_bfloat16 g_wlo[WTOT];

// ---------------- weight split + transpose: W[K][N] -> hi/lo [N][K] --------
__global__ void split_transpose(const float* __restrict__ W,
                                __nv_bfloat16* __restrict__ hi,
                                __nv_bfloat16* __restrict__ lo,
                                int K, int N)
{
    __shared__ float tile[32][33];
    const int k0 = blockIdx.y * 32, n0 = blockIdx.x * 32;
    const int tx = threadIdx.x, ty = threadIdx.y;   // 32 x 8
#pragma unroll
    for (int i = ty; i < 32; i += 8)
        tile[i][tx] = W[(k0 + i) * N + n0 + tx];
    __syncthreads();
#pragma unroll
    for (int i = ty; i < 32; i += 8) {
        float v = tile[tx][i];
        __nv_bfloat16 h = __float2bfloat16(v);
        float r = v - __bfloat162float(h);
        hi[(n0 + i) * (long)K + k0 + tx] = h;
        lo[(n0 + i) * (long)K + k0 + tx] = __float2bfloat16(r);
    }
}

// ---------------- split helper: float4 -> packed bf16 hi/lo ----------------
__device__ __forceinline__ void split4(float4 v, uint2& h, uint2& l)
{
    __nv_bfloat162 h0 = __floats2bfloat162_rn(v.x, v.y);
    __nv_bfloat162 h1 = __floats2bfloat162_rn(v.z, v.w);
    float2 f0 = __bfloat1622float2(h0);
    float2 f1 = __bfloat1622float2(h1);
    __nv_bfloat162 l0 = __floats2bfloat162_rn(v.x - f0.x, v.y - f0.y);
    __nv_bfloat162 l1 = __floats2bfloat162_rn(v.z - f1.x, v.w - f1.y);
    h.x = *(unsigned*)&h0; h.y = *(unsigned*)&h1;
    l.x = *(unsigned*)&l0; l.y = *(unsigned*)&l1;
}

__device__ __forceinline__ void mma16816(float* c, const unsigned* a,
                                         unsigned b0, unsigned b1)
{
    asm volatile(
        "mma.sync.aligned.m16n8k16.row.col.f32.bf16.bf16.f32 "
        "{%0,%1,%2,%3}, {%4,%5,%6,%7}, {%8,%9}, {%0,%1,%2,%3};\n"
        : "+f"(c[0]), "+f"(c[1]), "+f"(c[2]), "+f"(c[3])
        : "r"(a[0]), "r"(a[1]), "r"(a[2]), "r"(a[3]), "r"(b0), "r"(b1));
}

// ---------------- bf16-split tensor-core GEMM ------------------------------
// C[M][N] = A[M][K](fp32) @ W(pre-split bf16 [N][K]) + bias, 3-pass hi/lo.
// BM=128, BN=128, BK=32, 256 threads (8 warps, 4x2), warp tile 32x64.
#define GSTRIDE 40
__global__ __launch_bounds__(256) void gemm_bf16s(
    const float* __restrict__ A,
    const __nv_bfloat16* __restrict__ Bhi, const __nv_bfloat16* __restrict__ Blo,
    const float* __restrict__ bias, float* __restrict__ C,
    int M, int N, int K)
{
    __shared__ __align__(16) __nv_bfloat16 sm[4][128][GSTRIDE];
    // sm[0]=Ah  sm[1]=Al  sm[2]=Bh  sm[3]=Bl

    const int tid  = threadIdx.x;
    const int wid  = tid >> 5, lane = tid & 31;
    const int row0 = blockIdx.y * 128, col0 = blockIdx.x * 128;
    const int wm   = (wid >> 1) * 32, wn = (wid & 1) * 64;

    float acc[2][8][4];
#pragma unroll
    for (int t = 0; t < 2; t++)
#pragma unroll
        for (int n = 0; n < 8; n++)
#pragma unroll
            for (int j = 0; j < 4; j++) acc[t][n][j] = 0.f;

    // gmem load mapping
    const int a_r = tid >> 1, a_c = (tid & 1) * 16;   // A: 4 float4 / thread
    const int b_n = tid >> 1, b_c = (tid & 1) * 16;   // B: 2x(hi,lo) float4

    float4 av[4];
    float4 bhv[2], blv[2];

    // prefetch k0 = 0
#pragma unroll
    for (int t = 0; t < 4; t++)
        av[t] = *(const float4*)&A[(row0 + a_r) * (long)K + a_c + t * 4];
#pragma unroll
    for (int t = 0; t < 2; t++) {
        bhv[t] = *(const float4*)&Bhi[(col0 + b_n) * (long)K + b_c + t * 8];
        blv[t] = *(const float4*)&Blo[(col0 + b_n) * (long)K + b_c + t * 8];
    }

    for (int k0 = 0; k0 < K; k0 += 32) {
        __syncthreads();
        // store prefetched tile to smem (split A on the fly)
#pragma unroll
        for (int t = 0; t < 4; t++) {
            uint2 h, l;
            split4(av[t], h, l);
            *(uint2*)&sm[0][a_r][a_c + t * 4] = h;
            *(uint2*)&sm[1][a_r][a_c + t * 4] = l;
        }
#pragma unroll
        for (int t = 0; t < 2; t++) {
            *(float4*)&sm[2][b_n][b_c + t * 8] = bhv[t];
            *(float4*)&sm[3][b_n][b_c + t * 8] = blv[t];
        }
        __syncthreads();

        if (k0 + 32 < K) {
#pragma unroll
            for (int t = 0; t < 4; t++)
                av[t] = *(const float4*)&A[(row0 + a_r) * (long)K + k0 + 32 + a_c + t * 4];
#pragma unroll
            for (int t = 0; t < 2; t++) {
                bhv[t] = *(const float4*)&Bhi[(col0 + b_n) * (long)K + k0 + 32 + b_c + t * 8];
                blv[t] = *(const float4*)&Blo[(col0 + b_n) * (long)K + k0 + 32 + b_c + t * 8];
            }
        }

#pragma unroll
        for (int s = 0; s < 2; s++) {
            const int c = s * 16 + (lane & 3) * 2;
            unsigned afh[2][4], afl[2][4];
#pragma unroll
            for (int t = 0; t < 2; t++) {
                int r = wm + t * 16 + (lane >> 2);
                afh[t][0] = *(unsigned*)&sm[0][r][c];
                afh[t][1] = *(unsigned*)&sm[0][r + 8][c];
                afh[t][2] = *(unsigned*)&sm[0][r][c + 8];
                afh[t][3] = *(unsigned*)&sm[0][r + 8][c + 8];
                afl[t][0] = *(unsigned*)&sm[1][r][c];
                afl[t][1] = *(unsigned*)&sm[1][r + 8][c];
                afl[t][2] = *(unsigned*)&sm[1][r][c + 8];
                afl[t][3] = *(unsigned*)&sm[1][r + 8][c + 8];
            }
#pragma unroll
            for (int nt = 0; nt < 8; nt++) {
                int n = wn + nt * 8 + (lane >> 2);
                unsigned bh0 = *(unsigned*)&sm[2][n][c];
                unsigned bh1 = *(unsigned*)&sm[2][n][c + 8];
                unsigned bl0 = *(unsigned*)&sm[3][n][c];
                unsigned bl1 = *(unsigned*)&sm[3][n][c + 8];
#pragma unroll
                for (int t = 0; t < 2; t++) {
                    mma16816(acc[t][nt], afh[t], bh0, bh1);   // hi*hi
                    mma16816(acc[t][nt], afh[t], bl0, bl1);   // hi*lo
                    mma16816(acc[t][nt], afl[t], bh0, bh1);   // lo*hi
                }
            }
        }
    }

    // epilogue: bias + store
#pragma unroll
    for (int t = 0; t < 2; t++) {
        int gr = row0 + wm + t * 16 + (lane >> 2);
#pragma unroll
        for (int nt = 0; nt < 8; nt++) {
            int gc = col0 + wn + nt * 8 + (lane & 3) * 2;
            float2 bv = *(const float2*)&bias[gc];
            float2 o0 = make_float2(acc[t][nt][0] + bv.x, acc[t][nt][1] + bv.y);
            float2 o1 = make_float2(acc[t][nt][2] + bv.x, acc[t][nt][3] + bv.y);
            *(float2*)&C[(long)gr * N + gc]       = o0;
            *(float2*)&C[(long)(gr + 8) * N + gc] = o1;
        }
    }
}

// ---------------- fp32 tiled GEMM (kept for the tiny N=128 projections) ----
__global__ __launch_bounds__(256) void sgemm_bias(
    const float* __restrict__ A, const float* __restrict__ Bm,
    const float* __restrict__ bias, float* __restrict__ C,
    int M, int N, int K)
{
    __shared__ float As[16][128];
    __shared__ float Bs[16][64];
    const int tid  = threadIdx.x;
    const int ty   = tid >> 4;
    const int tx   = tid & 15;
    const int row0 = blockIdx.y * 128;
    const int col0 = blockIdx.x * 64;

    float acc[8][4];
#pragma unroll
    for (int i = 0; i < 8; i++)
#pragma unroll
        for (int j = 0; j < 4; j++) acc[i][j] = 0.f;

    const int ar  = tid >> 1;
    const int ac4 = (tid & 1) * 2;
    const int br  = tid >> 4;
    const int bc4 = tid & 15;

    for (int k0 = 0; k0 < K; k0 += 16) {
#pragma unroll
        for (int t = 0; t < 2; t++) {
            float4 v = *(const float4*)&A[(row0 + ar) * K + k0 + (ac4 + t) * 4];
            int c = (ac4 + t) * 4;
            As[c + 0][ar] = v.x; As[c + 1][ar] = v.y;
            As[c + 2][ar] = v.z; As[c + 3][ar] = v.w;
        }
        {
            float4 v = *(const float4*)&Bm[(k0 + br) * N + col0 + bc4 * 4];
            *(float4*)&Bs[br][bc4 * 4] = v;
        }
        __syncthreads();
#pragma unroll
        for (int k = 0; k < 16; k++) {
            float a[8], b[4];
            *(float4*)&a[0] = *(const float4*)&As[k][ty * 8];
            *(float4*)&a[4] = *(const float4*)&As[k][ty * 8 + 4];
            *(float4*)&b[0] = *(const float4*)&Bs[k][tx * 4];
#pragma unroll
            for (int i = 0; i < 8; i++)
#pragma unroll
                for (int j = 0; j < 4; j++) acc[i][j] += a[i] * b[j];
        }
        __syncthreads();
    }
    float4 bv = *(const float4*)&bias[col0 + tx * 4];
#pragma unroll
    for (int i = 0; i < 8; i++) {
        float4 o;
        o.x = acc[i][0] + bv.x; o.y = acc[i][1] + bv.y;
        o.z = acc[i][2] + bv.z; o.w = acc[i][3] + bv.w;
        *(float4*)&C[(row0 + ty * 8 + i) * N + col0 + tx * 4] = o;
    }
}

// ---------------- rope (in place) ------------------------------------------
__global__ void rope_kernel(float* __restrict__ x)
{
    int row = blockIdx.x;
    int d   = threadIdx.x;
    __shared__ float buf[128];
    buf[d] = x[row * D_ + d];
    __syncthreads();
    int i = d & 63;
    float inv = (float)exp(-(double)(2 * i) / 128.0 * 9.210340371976184);
    float ang = (float)(row & (S_ - 1)) * inv;
    float s, c;
    sincosf(ang, &s, &c);
    float y = (d < 64) ? (buf[d] * c - buf[d + 64] * s)
                       : (buf[d - 64] * s + buf[d] * c);
    x[row * D_ + d] = y;
}

// ---------------- flash attention (fp32) -----------------------------------
__global__ __launch_bounds__(256, 1) void mla_attn_kernel(
    const float* __restrict__ qc, const float* __restrict__ qr,
    const float* __restrict__ kc, const float* __restrict__ kr,
    const float* __restrict__ vc, const int* __restrict__ mask,
    float* __restrict__ ctx)
{
    __shared__ float Ks[32 * 256];
    __shared__ float Vs[32 * 128];

    const int tid = threadIdx.x;
    const int r   = tid >> 2;
    const int q4  = tid & 3;
    const int b   = blockIdx.z, h = blockIdx.y;
    const int sq  = blockIdx.x * 64 + r;
    const int rowq = b * S_ + sq;

    float4 qv[16];
#pragma unroll
    for (int d4 = 0; d4 < 16; d4++) {
        int chunk = q4 * 16 + ((d4 + 2 * q4) & 15);
        int dim   = chunk * 4;
        const float* src = (dim < 128)
            ? &qc[rowq * H_ + h * D_ + dim]
            : &qr[rowq * D_ + (dim - 128)];
        qv[d4] = *(const float4*)src;
    }

    float m = -1e30f, l = 0.f;
    float4 o[8];
#pragma unroll
    for (int i = 0; i < 8; i++) o[i] = make_float4(0.f, 0.f, 0.f, 0.f);

    const float scale = 0.08838834764831845f;

    for (int kt = 0; kt < S_ / 32; kt++) {
        const int s0 = kt * 32;
        __syncthreads();
#pragma unroll
        for (int t = 0; t < 8; t++) {
            int idx = tid + t * 256;
            int j   = idx >> 6;
            int dim = (idx & 63) * 4;
            int rowk = b * S_ + s0 + j;
            float4 v = (dim < 128)
                ? *(const float4*)&kc[rowk * H_ + h * D_ + dim]
                : *(const float4*)&kr[rowk * D_ + (dim - 128)];
            *(float4*)&Ks[j * 256 + dim] = v;
        }
#pragma unroll
        for (int t = 0; t < 4; t++) {
            int idx = tid + t * 256;
            int j   = idx >> 5;
            int dim = (idx & 31) * 4;
            int rowk = b * S_ + s0 + j;
            *(float4*)&Vs[j * 128 + dim] =
                *(const float4*)&vc[rowk * H_ + h * D_ + dim];
        }
        __syncthreads();

        float sc[32];
#pragma unroll
        for (int j = 0; j < 32; j++) {
            float4 a = make_float4(0.f, 0.f, 0.f, 0.f);
#pragma unroll
            for (int d4 = 0; d4 < 16; d4++) {
                int chunk = q4 * 16 + ((d4 + 2 * q4) & 15);
                float4 kv = *(const float4*)&Ks[j * 256 + chunk * 4];
                a.x += qv[d4].x * kv.x; a.y += qv[d4].y * kv.y;
                a.z += qv[d4].z * kv.z; a.w += qv[d4].w * kv.w;
            }
            float s = (a.x + a.y) + (a.z + a.w);
            s += __shfl_xor_sync(0xffffffffu, s, 1);
            s += __shfl_xor_sync(0xffffffffu, s, 2);
            s *= scale;
            if (mask[b * S_ + s0 + j] == 0) s = -1e30f;
            sc[j] = s;
        }

        float tmax = sc[0];
#pragma unroll
        for (int j = 1; j < 32; j++) tmax = fmaxf(tmax, sc[j]);
        float mnew = fmaxf(m, tmax);
        float corr = __expf(m - mnew);
        l *= corr;
#pragma unroll
        for (int i = 0; i < 8; i++) {
            o[i].x *= corr; o[i].y *= corr; o[i].z *= corr; o[i].w *= corr;
        }
#pragma unroll
        for (int j = 0; j < 32; j++) {
            float p = __expf(sc[j] - mnew);
            l += p;
#pragma unroll
            for (int i4 = 0; i4 < 8; i4++) {
                int chunk = q4 * 8 + ((i4 + 2 * q4) & 7);
                float4 v = *(const float4*)&Vs[j * 128 + chunk * 4];
                o[i4].x += p * v.x; o[i4].y += p * v.y;
                o[i4].z += p * v.z; o[i4].w += p * v.w;
            }
        }
        m = mnew;
    }

    float inv_l = 1.0f / l;
#pragma unroll
    for (int i4 = 0; i4 < 8; i4++) {
        int chunk = q4 * 8 + ((i4 + 2 * q4) & 7);
        float4 ov = o[i4];
        ov.x *= inv_l; ov.y *= inv_l; ov.z *= inv_l; ov.w *= inv_l;
        *(float4*)&ctx[rowq * H_ + h * D_ + chunk * 4] = ov;
    }
}

// ---------------- launch ----------------------------------------------------
extern "C" void kernel_launch(void* const* d_in, const int* in_sizes, int n_in,
                              void* d_out, int out_size)
{
    const float* hs    = (const float*)d_in[0];
    const int*   mask  = (const int*)  d_in[1];
    const float* W_DKV = (const float*)d_in[2];  const float* b_DKV = (const float*)d_in[3];
    const float* W_DQ  = (const float*)d_in[4];  const float* b_DQ  = (const float*)d_in[5];
    const float* W_UK  = (const float*)d_in[6];  const float* b_UK  = (const float*)d_in[7];
    const float* W_UV  = (const float*)d_in[8];  const float* b_UV  = (const float*)d_in[9];
    const float* W_UQ  = (const float*)d_in[10]; const float* b_UQ  = (const float*)d_in[11];
    const float* W_KR  = (const float*)d_in[12]; const float* b_KR  = (const float*)d_in[13];
    const float* W_QR  = (const float*)d_in[14]; const float* b_QR  = (const float*)d_in[15];
    const float* W_O   = (const float*)d_in[16]; const float* b_O   = (const float*)d_in[17];
    float* out = (float*)d_out;

    float *ckv, *cq, *kc, *vc, *qc, *kr, *qr, *ctx;
    __nv_bfloat16 *whi, *wlo;
    cudaGetSymbolAddress((void**)&ckv, g_ckv);
    cudaGetSymbolAddress((void**)&cq,  g_cq);
    cudaGetSymbolAddress((void**)&kc,  g_kc);
    cudaGetSymbolAddress((void**)&vc,  g_vc);
    cudaGetSymbolAddress((void**)&qc,  g_qc);
    cudaGetSymbolAddress((void**)&kr,  g_kr);
    cudaGetSymbolAddress((void**)&qr,  g_qr);
    cudaGetSymbolAddress((void**)&ctx, g_ctx);
    cudaGetSymbolAddress((void**)&whi, g_whi);
    cudaGetSymbolAddress((void**)&wlo, g_wlo);

    const dim3 blk(256);
    const dim3 tblk(32, 8);

    // weight split+transpose (runs every replay; ~15us total)
    split_transpose<<<dim3(LAT_/32, H_/32),  tblk>>>(W_DKV, whi+OFF_DKV, wlo+OFF_DKV, H_,  LAT_);
    split_transpose<<<dim3(LAT_/32, H_/32),  tblk>>>(W_DQ,  whi+OFF_DQ,  wlo+OFF_DQ,  H_,  LAT_);
    split_transpose<<<dim3(H_/32,  LAT_/32), tblk>>>(W_UK,  whi+OFF_UK,  wlo+OFF_UK,  LAT_, H_);
    split_transpose<<<dim3(H_/32,  LAT_/32), tblk>>>(W_UV,  whi+OFF_UV,  wlo+OFF_UV,  LAT_, H_);
    split_transpose<<<dim3(H_/32,  LAT_/32), tblk>>>(W_UQ,  whi+OFF_UQ,  wlo+OFF_UQ,  LAT_, H_);
    split_transpose<<<dim3(H_/32,  H_/32),   tblk>>>(W_O,   whi+OFF_O,   wlo+OFF_O,   H_,   H_);

    // down-projections (tensor cores) + rope projections (fp32, tiny)
    gemm_bf16s<<<dim3(LAT_/128, MS_/128), blk>>>(hs, whi+OFF_DKV, wlo+OFF_DKV, b_DKV, ckv, MS_, LAT_, H_);
    gemm_bf16s<<<dim3(LAT_/128, MS_/128), blk>>>(hs, whi+OFF_DQ,  wlo+OFF_DQ,  b_DQ,  cq,  MS_, LAT_, H_);
    sgemm_bias<<<dim3(D_/64,   MS_/128), blk>>>(hs, W_KR, b_KR, kr, MS_, D_, H_);
    sgemm_bias<<<dim3(D_/64,   MS_/128), blk>>>(hs, W_QR, b_QR, qr, MS_, D_, H_);
    rope_kernel<<<MS_, 128>>>(kr);
    rope_kernel<<<MS_, 128>>>(qr);

    // up-projections (tensor cores)
    gemm_bf16s<<<dim3(H_/128, MS_/128), blk>>>(ckv, whi+OFF_UK, wlo+OFF_UK, b_UK, kc, MS_, H_, LAT_);
    gemm_bf16s<<<dim3(H_/128, MS_/128), blk>>>(ckv, whi+OFF_UV, wlo+OFF_UV, b_UV, vc, MS_, H_, LAT_);
    gemm_bf16s<<<dim3(H_/128, MS_/128), blk>>>(cq,  whi+OFF_UQ, wlo+OFF_UQ, b_UQ, qc, MS_, H_, LAT_);

    // attention (fp32 — next optimization target)
    mla_attn_kernel<<<dim3(S_/64, NH_, B_), 256>>>(qc, qr, kc, kr, vc, mask, ctx);

    // output projection (tensor cores)
    gemm_bf16s<<<dim3(H_/128, MS_/128), blk>>>(ctx, whi+OFF_O, wlo+OFF_O, b_O, out, MS_, H_, H_);
}

// round 9
// speedup vs baseline: 2.6181x; 2.3741x over previous
#include <cuda_runtime.h>
#include <cuda_bf16.h>
#include <math.h>

#define B_   2
#define S_   2048
#define H_   2048
#define NH_  16
#define D_   128
#define LAT_ 512
#define MS_  (B_*S_)   // 4096 rows total

// ---------------- scratch (device globals; no allocation allowed) ----------
__device__ float g_ckv[MS_*LAT_];
__device__ float g_cq [MS_*LAT_];
__device__ float g_kr [MS_*D_];
__device__ float g_qr [MS_*D_];
__device__ float g_ctx[MS_*H_];

// pre-split bf16 activations for attention
__device__ __nv_bfloat16 g_khi [MS_*H_], g_klo [MS_*H_];   // K_c  [row][H]
__device__ __nv_bfloat16 g_qhi [MS_*H_], g_qlo [MS_*H_];   // Q_c  [row][H]
__device__ __nv_bfloat16 g_vthi[MS_*H_], g_vtlo[MS_*H_];   // V^T  [H][MS]
__device__ __nv_bfloat16 g_krh [MS_*D_], g_krl [MS_*D_];   // rope(K_r)
__device__ __nv_bfloat16 g_qrh [MS_*D_], g_qrl [MS_*D_];   // rope(Q_r)

// pre-split / transposed bf16 weights ([N][K] layout), hi + lo residual
#define OFF_DKV 0
#define OFF_DQ  1048576
#define OFF_UK  2097152
#define OFF_UV  3145728
#define OFF_UQ  4194304
#define OFF_O   5242880
#define OFF_KR  9437184
#define OFF_QR  9699328
#define WTOT    9961472
__device__ __nv_bfloat16 g_whi[WTOT];
__device__ __nv_bfloat16 g_wlo[WTOT];

// ---------------- weight split + transpose: W[K][N] -> hi/lo [N][K] --------
__global__ void split_transpose(const float* __restrict__ W,
                                __nv_bfloat16* __restrict__ hi,
                                __nv_bfloat16* __restrict__ lo,
                                int K, int N)
{
    __shared__ float tile[32][33];
    const int k0 = blockIdx.y * 32, n0 = blockIdx.x * 32;
    const int tx = threadIdx.x, ty = threadIdx.y;   // 32 x 8
#pragma unroll
    for (int i = ty; i < 32; i += 8)
        tile[i][tx] = W[(k0 + i) * N + n0 + tx];
    __syncthreads();
#pragma unroll
    for (int i = ty; i < 32; i += 8) {
        float v = tile[tx][i];
        __nv_bfloat16 h = __float2bfloat16(v);
        float r = v - __bfloat162float(h);
        hi[(n0 + i) * (long)K + k0 + tx] = h;
        lo[(n0 + i) * (long)K + k0 + tx] = __float2bfloat16(r);
    }
}

// ---------------- split helper: float4 -> packed bf16 hi/lo ----------------
__device__ __forceinline__ void split4(float4 v, uint2& h, uint2& l)
{
    __nv_bfloat162 h0 = __floats2bfloat162_rn(v.x, v.y);
    __nv_bfloat162 h1 = __floats2bfloat162_rn(v.z, v.w);
    float2 f0 = __bfloat1622float2(h0);
    float2 f1 = __bfloat1622float2(h1);
    __nv_bfloat162 l0 = __floats2bfloat162_rn(v.x - f0.x, v.y - f0.y);
    __nv_bfloat162 l1 = __floats2bfloat162_rn(v.z - f1.x, v.w - f1.y);
    h.x = *(unsigned*)&h0; h.y = *(unsigned*)&h1;
    l.x = *(unsigned*)&l0; l.y = *(unsigned*)&l1;
}

__device__ __forceinline__ void mma16816(float* c, const unsigned* a,
                                         unsigned b0, unsigned b1)
{
    asm volatile(
        "mma.sync.aligned.m16n8k16.row.col.f32.bf16.bf16.f32 "
        "{%0,%1,%2,%3}, {%4,%5,%6,%7}, {%8,%9}, {%0,%1,%2,%3};\n"
        : "+f"(c[0]), "+f"(c[1]), "+f"(c[2]), "+f"(c[3])
        : "r"(a[0]), "r"(a[1]), "r"(a[2]), "r"(a[3]), "r"(b0), "r"(b1));
}

// ---------------- bf16-split tensor-core GEMM ------------------------------
// C[M][N] = A[M][K](fp32) @ W(pre-split bf16 [N][K]) + bias, 3-pass hi/lo.
// MODE 0: fp32 C. MODE 1: bf16 hi/lo row-major. MODE 2: bf16 hi/lo transposed
// ([N][MS_] layout, for V^T).
#define GSTRIDE 40
template<int MODE>
__global__ __launch_bounds__(256) void gemm_bf16s(
    const float* __restrict__ A,
    const __nv_bfloat16* __restrict__ Bhi, const __nv_bfloat16* __restrict__ Blo,
    const float* __restrict__ bias, float* __restrict__ C,
    __nv_bfloat16* __restrict__ Chi, __nv_bfloat16* __restrict__ Clo,
    int M, int N, int K)
{
    __shared__ __align__(16) __nv_bfloat16 sm[4][128][GSTRIDE];
    // sm[0]=Ah  sm[1]=Al  sm[2]=Bh  sm[3]=Bl

    const int tid  = threadIdx.x;
    const int wid  = tid >> 5, lane = tid & 31;
    const int row0 = blockIdx.y * 128, col0 = blockIdx.x * 128;
    const int wm   = (wid >> 1) * 32, wn = (wid & 1) * 64;

    float acc[2][8][4];
#pragma unroll
    for (int t = 0; t < 2; t++)
#pragma unroll
        for (int n = 0; n < 8; n++)
#pragma unroll
            for (int j = 0; j < 4; j++) acc[t][n][j] = 0.f;

    const int a_r = tid >> 1, a_c = (tid & 1) * 16;
    const int b_n = tid >> 1, b_c = (tid & 1) * 16;

    float4 av[4];
    float4 bhv[2], blv[2];

#pragma unroll
    for (int t = 0; t < 4; t++)
        av[t] = *(const float4*)&A[(row0 + a_r) * (long)K + a_c + t * 4];
#pragma unroll
    for (int t = 0; t < 2; t++) {
        bhv[t] = *(const float4*)&Bhi[(col0 + b_n) * (long)K + b_c + t * 8];
        blv[t] = *(const float4*)&Blo[(col0 + b_n) * (long)K + b_c + t * 8];
    }

    for (int k0 = 0; k0 < K; k0 += 32) {
        __syncthreads();
#pragma unroll
        for (int t = 0; t < 4; t++) {
            uint2 h, l;
            split4(av[t], h, l);
            *(uint2*)&sm[0][a_r][a_c + t * 4] = h;
            *(uint2*)&sm[1][a_r][a_c + t * 4] = l;
        }
#pragma unroll
        for (int t = 0; t < 2; t++) {
            *(float4*)&sm[2][b_n][b_c + t * 8] = bhv[t];
            *(float4*)&sm[3][b_n][b_c + t * 8] = blv[t];
        }
        __syncthreads();

        if (k0 + 32 < K) {
#pragma unroll
            for (int t = 0; t < 4; t++)
                av[t] = *(const float4*)&A[(row0 + a_r) * (long)K + k0 + 32 + a_c + t * 4];
#pragma unroll
            for (int t = 0; t < 2; t++) {
                bhv[t] = *(const float4*)&Bhi[(col0 + b_n) * (long)K + k0 + 32 + b_c + t * 8];
                blv[t] = *(const float4*)&Blo[(col0 + b_n) * (long)K + k0 + 32 + b_c + t * 8];
            }
        }

#pragma unroll
        for (int s = 0; s < 2; s++) {
            const int c = s * 16 + (lane & 3) * 2;
            unsigned afh[2][4], afl[2][4];
#pragma unroll
            for (int t = 0; t < 2; t++) {
                int r = wm + t * 16 + (lane >> 2);
                afh[t][0] = *(unsigned*)&sm[0][r][c];
                afh[t][1] = *(unsigned*)&sm[0][r + 8][c];
                afh[t][2] = *(unsigned*)&sm[0][r][c + 8];
                afh[t][3] = *(unsigned*)&sm[0][r + 8][c + 8];
                afl[t][0] = *(unsigned*)&sm[1][r][c];
                afl[t][1] = *(unsigned*)&sm[1][r + 8][c];
                afl[t][2] = *(unsigned*)&sm[1][r][c + 8];
                afl[t][3] = *(unsigned*)&sm[1][r + 8][c + 8];
            }
#pragma unroll
            for (int nt = 0; nt < 8; nt++) {
                int n = wn + nt * 8 + (lane >> 2);
                unsigned bh0 = *(unsigned*)&sm[2][n][c];
                unsigned bh1 = *(unsigned*)&sm[2][n][c + 8];
                unsigned bl0 = *(unsigned*)&sm[3][n][c];
                unsigned bl1 = *(unsigned*)&sm[3][n][c + 8];
#pragma unroll
                for (int t = 0; t < 2; t++) {
                    mma16816(acc[t][nt], afh[t], bh0, bh1);
                    mma16816(acc[t][nt], afh[t], bl0, bl1);
                    mma16816(acc[t][nt], afl[t], bh0, bh1);
                }
            }
        }
    }

#pragma unroll
    for (int t = 0; t < 2; t++) {
        int gr = row0 + wm + t * 16 + (lane >> 2);
#pragma unroll
        for (int nt = 0; nt < 8; nt++) {
            int gc = col0 + wn + nt * 8 + (lane & 3) * 2;
            float2 bv = *(const float2*)&bias[gc];
            float v0 = acc[t][nt][0] + bv.x, v1 = acc[t][nt][1] + bv.y;
            float v2 = acc[t][nt][2] + bv.x, v3 = acc[t][nt][3] + bv.y;
            if (MODE == 0) {
                *(float2*)&C[(long)gr * N + gc]       = make_float2(v0, v1);
                *(float2*)&C[(long)(gr + 8) * N + gc] = make_float2(v2, v3);
            } else if (MODE == 1) {
                __nv_bfloat162 h01 = __floats2bfloat162_rn(v0, v1);
                float2 f01 = __bfloat1622float2(h01);
                __nv_bfloat162 q01 = __floats2bfloat162_rn(v0 - f01.x, v1 - f01.y);
                __nv_bfloat162 h23 = __floats2bfloat162_rn(v2, v3);
                float2 f23 = __bfloat1622float2(h23);
                __nv_bfloat162 q23 = __floats2bfloat162_rn(v2 - f23.x, v3 - f23.y);
                *(__nv_bfloat162*)&Chi[(long)gr * N + gc]       = h01;
                *(__nv_bfloat162*)&Clo[(long)gr * N + gc]       = q01;
                *(__nv_bfloat162*)&Chi[(long)(gr + 8) * N + gc] = h23;
                *(__nv_bfloat162*)&Clo[(long)(gr + 8) * N + gc] = q23;
            } else {
                // transposed: out[gc][gr], leading dim MS_
                float vs[4] = {v0, v1, v2, v3};
#pragma unroll
                for (int q = 0; q < 4; q++) {
                    long idx = (long)(gc + (q & 1)) * MS_ + gr + (q >> 1) * 8;
                    __nv_bfloat16 hh = __float2bfloat16(vs[q]);
                    Chi[idx] = hh;
                    Clo[idx] = __float2bfloat16(vs[q] - __bfloat162float(hh));
                }
            }
        }
    }
}

// ---------------- rope: fp32 in -> bf16 hi/lo out --------------------------
__global__ void rope_kernel(const float* __restrict__ x,
                            __nv_bfloat16* __restrict__ oh,
                            __nv_bfloat16* __restrict__ ol)
{
    int row = blockIdx.x;
    int d   = threadIdx.x;
    __shared__ float buf[128];
    buf[d] = x[row * D_ + d];
    __syncthreads();
    int i = d & 63;
    float inv = (float)exp(-(double)(2 * i) / 128.0 * 9.210340371976184);
    float ang = (float)(row & (S_ - 1)) * inv;
    float s, c;
    sincosf(ang, &s, &c);
    float y = (d < 64) ? (buf[d] * c - buf[d + 64] * s)
                       : (buf[d - 64] * s + buf[d] * c);
    __nv_bfloat16 h = __float2bfloat16(y);
    oh[row * D_ + d] = h;
    ol[row * D_ + d] = __float2bfloat16(y - __bfloat162float(h));
}

// ---------------- tensor-core flash attention (bf16 3-pass split) ----------
// grid (S/64, NH, B), 128 threads (4 warps, 16 q-rows each). 64-key tiles.
// QK dim 256 = [k_c | rope(k_r)], V dim 128. smem strides 264/72 bf16 give
// conflict-free fragment reads (banks 4*(lane>>2)+(lane&3)).
#define AT_SMEM 190720
__global__ __launch_bounds__(128, 1) void mla_attn_mma(
    const __nv_bfloat16* __restrict__ qhi, const __nv_bfloat16* __restrict__ qlo,
    const __nv_bfloat16* __restrict__ qrh, const __nv_bfloat16* __restrict__ qrl,
    const __nv_bfloat16* __restrict__ khi, const __nv_bfloat16* __restrict__ klo,
    const __nv_bfloat16* __restrict__ krh, const __nv_bfloat16* __restrict__ krl,
    const __nv_bfloat16* __restrict__ vth, const __nv_bfloat16* __restrict__ vtl,
    const int* __restrict__ mask, float* __restrict__ ctx)
{
    extern __shared__ __align__(16) char smx[];
    __nv_bfloat16* QH = (__nv_bfloat16*)smx;
    __nv_bfloat16* QL = QH + 64 * 264;
    __nv_bfloat16* KH = QL + 64 * 264;
    __nv_bfloat16* KL = KH + 64 * 264;
    __nv_bfloat16* VH = KL + 64 * 264;
    __nv_bfloat16* VL = VH + 128 * 72;
    __nv_bfloat16* PH = VL + 128 * 72;
    __nv_bfloat16* PL = PH + 64 * 72;
    float*         MB = (float*)(PL + 64 * 72);

    const int t    = threadIdx.x;
    const int lane = t & 31, w = t >> 5;
    const int b = blockIdx.z, h = blockIdx.y;
    const int q0 = blockIdx.x * 64;
    const int r0 = w * 16;
    const int ru = lane >> 2, rv = lane & 3;

    // ---- load Q tile (once) ----
    {
        int r = t & 63, half = t >> 6;
        long rowq = (long)(b * S_ + q0 + r);
        const uint4* sH = half ? (const uint4*)&qrh[rowq * D_]
                               : (const uint4*)&qhi[rowq * H_ + h * D_];
        const uint4* sL = half ? (const uint4*)&qrl[rowq * D_]
                               : (const uint4*)&qlo[rowq * H_ + h * D_];
        uint4* dH = (uint4*)(QH + r * 264 + half * 128);
        uint4* dL = (uint4*)(QL + r * 264 + half * 128);
#pragma unroll
        for (int c = 0; c < 16; c++) { dH[c] = sH[c]; dL[c] = sL[c]; }
    }

    float oacc[16][4];
#pragma unroll
    for (int i = 0; i < 16; i++)
#pragma unroll
        for (int j = 0; j < 4; j++) oacc[i][j] = 0.f;
    float m0 = -1e30f, m1 = -1e30f, l0 = 0.f, l1 = 0.f;
    const float scale = 0.08838834764831845f;   // 1/sqrt(128)

    const unsigned* QHw = (const unsigned*)QH;
    const unsigned* QLw = (const unsigned*)QL;
    const unsigned* KHw = (const unsigned*)KH;
    const unsigned* KLw = (const unsigned*)KL;
    const unsigned* VHw = (const unsigned*)VH;
    const unsigned* VLw = (const unsigned*)VL;
    unsigned* PHw = (unsigned*)PH;
    unsigned* PLw = (unsigned*)PL;

    for (int s0 = 0; s0 < S_; s0 += 64) {
        __syncthreads();
        // ---- K tile ----
        {
            int r = t & 63, half = t >> 6;
            long rowk = (long)(b * S_ + s0 + r);
            const uint4* sH = half ? (const uint4*)&krh[rowk * D_]
                                   : (const uint4*)&khi[rowk * H_ + h * D_];
            const uint4* sL = half ? (const uint4*)&krl[rowk * D_]
                                   : (const uint4*)&klo[rowk * H_ + h * D_];
            uint4* dH = (uint4*)(KH + r * 264 + half * 128);
            uint4* dL = (uint4*)(KL + r * 264 + half * 128);
#pragma unroll
            for (int c = 0; c < 16; c++) { dH[c] = sH[c]; dL[c] = sL[c]; }
        }
        // ---- V^T tile ----
        {
            long vrow = (long)(h * D_ + t);
            const uint4* sH = (const uint4*)&vth[vrow * MS_ + b * S_ + s0];
            const uint4* sL = (const uint4*)&vtl[vrow * MS_ + b * S_ + s0];
            uint4* dH = (uint4*)(VH + t * 72);
            uint4* dL = (uint4*)(VL + t * 72);
#pragma unroll
            for (int c = 0; c < 8; c++) { dH[c] = sH[c]; dL[c] = sL[c]; }
        }
        if (t < 64) MB[t] = mask[b * S_ + s0 + t] ? 0.f : -1e30f;
        __syncthreads();

        // ---- QK^T (3-pass) ----
        float sacc[8][4];
#pragma unroll
        for (int i = 0; i < 8; i++)
#pragma unroll
            for (int j = 0; j < 4; j++) sacc[i][j] = 0.f;
#pragma unroll 1
        for (int ch = 0; ch < 16; ch++) {
            unsigned ah[4], al[4];
            int ab = (r0 + ru) * 132 + ch * 8 + rv;
            ah[0] = QHw[ab];     ah[1] = QHw[ab + 8*132];
            ah[2] = QHw[ab + 4]; ah[3] = QHw[ab + 8*132 + 4];
            al[0] = QLw[ab];     al[1] = QLw[ab + 8*132];
            al[2] = QLw[ab + 4]; al[3] = QLw[ab + 8*132 + 4];
#pragma unroll
            for (int nt = 0; nt < 8; nt++) {
                int bb = (nt * 8 + ru) * 132 + ch * 8 + rv;
                unsigned bh0 = KHw[bb], bh1 = KHw[bb + 4];
                unsigned bl0 = KLw[bb], bl1 = KLw[bb + 4];
                mma16816(sacc[nt], ah, bh0, bh1);
                mma16816(sacc[nt], ah, bl0, bl1);
                mma16816(sacc[nt], al, bh0, bh1);
            }
        }

        // ---- online softmax ----
        float mx0 = -1e30f, mx1 = -1e30f;
#pragma unroll
        for (int nt = 0; nt < 8; nt++) {
            int col = nt * 8 + rv * 2;
            float mb0 = MB[col], mb1 = MB[col + 1];
            sacc[nt][0] = sacc[nt][0] * scale + mb0;
            sacc[nt][1] = sacc[nt][1] * scale + mb1;
            sacc[nt][2] = sacc[nt][2] * scale + mb0;
            sacc[nt][3] = sacc[nt][3] * scale + mb1;
            mx0 = fmaxf(mx0, fmaxf(sacc[nt][0], sacc[nt][1]));
            mx1 = fmaxf(mx1, fmaxf(sacc[nt][2], sacc[nt][3]));
        }
        mx0 = fmaxf(mx0, __shfl_xor_sync(0xffffffffu, mx0, 1));
        mx0 = fmaxf(mx0, __shfl_xor_sync(0xffffffffu, mx0, 2));
        mx1 = fmaxf(mx1, __shfl_xor_sync(0xffffffffu, mx1, 1));
        mx1 = fmaxf(mx1, __shfl_xor_sync(0xffffffffu, mx1, 2));
        float mn0 = fmaxf(m0, mx0), mn1 = fmaxf(m1, mx1);
        float cr0 = __expf(m0 - mn0), cr1 = __expf(m1 - mn1);
        m0 = mn0; m1 = mn1;
        l0 *= cr0; l1 *= cr1;
#pragma unroll
        for (int nt = 0; nt < 16; nt++) {
            oacc[nt][0] *= cr0; oacc[nt][1] *= cr0;
            oacc[nt][2] *= cr1; oacc[nt][3] *= cr1;
        }
        float rs0 = 0.f, rs1 = 0.f;
#pragma unroll
        for (int nt = 0; nt < 8; nt++) {
            float p0 = __expf(sacc[nt][0] - mn0), p1 = __expf(sacc[nt][1] - mn0);
            float p2 = __expf(sacc[nt][2] - mn1), p3 = __expf(sacc[nt][3] - mn1);
            rs0 += p0 + p1; rs1 += p2 + p3;
            __nv_bfloat162 h01 = __floats2bfloat162_rn(p0, p1);
            float2 f01 = __bfloat1622float2(h01);
            __nv_bfloat162 q01 = __floats2bfloat162_rn(p0 - f01.x, p1 - f01.y);
            __nv_bfloat162 h23 = __floats2bfloat162_rn(p2, p3);
            float2 f23 = __bfloat1622float2(h23);
            __nv_bfloat162 q23 = __floats2bfloat162_rn(p2 - f23.x, p3 - f23.y);
            int w0 = (r0 + ru) * 36 + nt * 4 + rv;
            int w1 = (r0 + ru + 8) * 36 + nt * 4 + rv;
            PHw[w0] = *(unsigned*)&h01; PLw[w0] = *(unsigned*)&q01;
            PHw[w1] = *(unsigned*)&h23; PLw[w1] = *(unsigned*)&q23;
        }
        rs0 += __shfl_xor_sync(0xffffffffu, rs0, 1);
        rs0 += __shfl_xor_sync(0xffffffffu, rs0, 2);
        rs1 += __shfl_xor_sync(0xffffffffu, rs1, 1);
        rs1 += __shfl_xor_sync(0xffffffffu, rs1, 2);
        l0 += rs0; l1 += rs1;
        __syncwarp();

        // ---- P @ V (3-pass) ----
#pragma unroll 1
        for (int ch = 0; ch < 4; ch++) {
            unsigned ph[4], pl[4];
            int ab = (r0 + ru) * 36 + ch * 8 + rv;
            ph[0] = PHw[ab];     ph[1] = PHw[ab + 8*36];
            ph[2] = PHw[ab + 4]; ph[3] = PHw[ab + 8*36 + 4];
            pl[0] = PLw[ab];     pl[1] = PLw[ab + 8*36];
            pl[2] = PLw[ab + 4]; pl[3] = PLw[ab + 8*36 + 4];
#pragma unroll
            for (int nt = 0; nt < 16; nt++) {
                int bb = (nt * 8 + ru) * 36 + ch * 8 + rv;
                unsigned vh0 = VHw[bb], vh1 = VHw[bb + 4];
                unsigned vl0 = VLw[bb], vl1 = VLw[bb + 4];
                mma16816(oacc[nt], ph, vh0, vh1);
                mma16816(oacc[nt], ph, vl0, vl1);
                mma16816(oacc[nt], pl, vh0, vh1);
            }
        }
    }

    float inv0 = 1.f / l0, inv1 = 1.f / l1;
    long row0 = (long)(b * S_ + q0 + r0 + ru);
#pragma unroll
    for (int nt = 0; nt < 16; nt++) {
        int d0 = nt * 8 + rv * 2;
        *(float2*)&ctx[row0 * H_ + h * D_ + d0] =
            make_float2(oacc[nt][0] * inv0, oacc[nt][1] * inv0);
        *(float2*)&ctx[(row0 + 8) * H_ + h * D_ + d0] =
            make_float2(oacc[nt][2] * inv1, oacc[nt][3] * inv1);
    }
}

// ---------------- launch ----------------------------------------------------
extern "C" void kernel_launch(void* const* d_in, const int* in_sizes, int n_in,
                              void* d_out, int out_size)
{
    const float* hs    = (const float*)d_in[0];
    const int*   mask  = (const int*)  d_in[1];
    const float* W_DKV = (const float*)d_in[2];  const float* b_DKV = (const float*)d_in[3];
    const float* W_DQ  = (const float*)d_in[4];  const float* b_DQ  = (const float*)d_in[5];
    const float* W_UK  = (const float*)d_in[6];  const float* b_UK  = (const float*)d_in[7];
    const float* W_UV  = (const float*)d_in[8];  const float* b_UV  = (const float*)d_in[9];
    const float* W_UQ  = (const float*)d_in[10]; const float* b_UQ  = (const float*)d_in[11];
    const float* W_KR  = (const float*)d_in[12]; const float* b_KR  = (const float*)d_in[13];
    const float* W_QR  = (const float*)d_in[14]; const float* b_QR  = (const float*)d_in[15];
    const float* W_O   = (const float*)d_in[16]; const float* b_O   = (const float*)d_in[17];
    float* out = (float*)d_out;

    float *ckv, *cq, *kr, *qr, *ctx;
    __nv_bfloat16 *whi, *wlo;
    __nv_bfloat16 *khi, *klo, *qhi, *qlo, *vthi, *vtlo, *krh, *krl, *qrh, *qrl;
    cudaGetSymbolAddress((void**)&ckv,  g_ckv);
    cudaGetSymbolAddress((void**)&cq,   g_cq);
    cudaGetSymbolAddress((void**)&kr,   g_kr);
    cudaGetSymbolAddress((void**)&qr,   g_qr);
    cudaGetSymbolAddress((void**)&ctx,  g_ctx);
    cudaGetSymbolAddress((void**)&whi,  g_whi);
    cudaGetSymbolAddress((void**)&wlo,  g_wlo);
    cudaGetSymbolAddress((void**)&khi,  g_khi);
    cudaGetSymbolAddress((void**)&klo,  g_klo);
    cudaGetSymbolAddress((void**)&qhi,  g_qhi);
    cudaGetSymbolAddress((void**)&qlo,  g_qlo);
    cudaGetSymbolAddress((void**)&vthi, g_vthi);
    cudaGetSymbolAddress((void**)&vtlo, g_vtlo);
    cudaGetSymbolAddress((void**)&krh,  g_krh);
    cudaGetSymbolAddress((void**)&krl,  g_krl);
    cudaGetSymbolAddress((void**)&qrh,  g_qrh);
    cudaGetSymbolAddress((void**)&qrl,  g_qrl);

    cudaFuncSetAttribute(mla_attn_mma,
                         cudaFuncAttributeMaxDynamicSharedMemorySize, AT_SMEM);

    const dim3 blk(256);
    const dim3 tblk(32, 8);

    // ordered so launch #6 (ncu -s 5 -c 1 capture) is the big bf16 GEMM
    split_transpose<<<dim3(LAT_/32, H_/32),  tblk>>>(W_DKV, whi+OFF_DKV, wlo+OFF_DKV, H_,  LAT_); // 1
    split_transpose<<<dim3(H_/32,  LAT_/32), tblk>>>(W_UK,  whi+OFF_UK,  wlo+OFF_UK,  LAT_, H_);  // 2
    split_transpose<<<dim3(H_/32,  LAT_/32), tblk>>>(W_UV,  whi+OFF_UV,  wlo+OFF_UV,  LAT_, H_);  // 3
    gemm_bf16s<0><<<dim3(LAT_/128, MS_/128), blk>>>(hs, whi+OFF_DKV, wlo+OFF_DKV, b_DKV,
                                                    ckv, nullptr, nullptr, MS_, LAT_, H_);         // 4
    split_transpose<<<dim3(H_/32,  LAT_/32), tblk>>>(W_UQ,  whi+OFF_UQ,  wlo+OFF_UQ,  LAT_, H_);  // 5
    gemm_bf16s<1><<<dim3(H_/128, MS_/128), blk>>>(ckv, whi+OFF_UK, wlo+OFF_UK, b_UK,
                                                  nullptr, khi, klo, MS_, H_, LAT_);               // 6 (profiled)
    gemm_bf16s<2><<<dim3(H_/128, MS_/128), blk>>>(ckv, whi+OFF_UV, wlo+OFF_UV, b_UV,
                                                  nullptr, vthi, vtlo, MS_, H_, LAT_);             // 7
    split_transpose<<<dim3(LAT_/32, H_/32),  tblk>>>(W_DQ, whi+OFF_DQ, wlo+OFF_DQ, H_, LAT_);     // 8
    gemm_bf16s<0><<<dim3(LAT_/128, MS_/128), blk>>>(hs, whi+OFF_DQ, wlo+OFF_DQ, b_DQ,
                                                    cq, nullptr, nullptr, MS_, LAT_, H_);          // 9
    gemm_bf16s<1><<<dim3(H_/128, MS_/128), blk>>>(cq, whi+OFF_UQ, wlo+OFF_UQ, b_UQ,
                                                  nullptr, qhi, qlo, MS_, H_, LAT_);               // 10
    split_transpose<<<dim3(D_/32, H_/32), tblk>>>(W_KR, whi+OFF_KR, wlo+OFF_KR, H_, D_);          // 11
    gemm_bf16s<0><<<dim3(1, MS_/128), blk>>>(hs, whi+OFF_KR, wlo+OFF_KR, b_KR,
                                             kr, nullptr, nullptr, MS_, D_, H_);                   // 12
    split_transpose<<<dim3(D_/32, H_/32), tblk>>>(W_QR, whi+OFF_QR, wlo+OFF_QR, H_, D_);          // 13
    gemm_bf16s<0><<<dim3(1, MS_/128), blk>>>(hs, whi+OFF_QR, wlo+OFF_QR, b_QR,
                                             qr, nullptr, nullptr, MS_, D_, H_);                   // 14
    rope_kernel<<<MS_, 128>>>(kr, krh, krl);                                                       // 15
    rope_kernel<<<MS_, 128>>>(qr, qrh, qrl);                                                       // 16
    split_transpose<<<dim3(H_/32, H_/32), tblk>>>(W_O, whi+OFF_O, wlo+OFF_O, H_, H_);             // 17

    mla_attn_mma<<<dim3(S_/64, NH_, B_), 128, AT_SMEM>>>(
        qhi, qlo, qrh, qrl, khi, klo, krh, krl, vthi, vtlo, mask, ctx);                            // 18

    gemm_bf16s<0><<<dim3(H_/128, MS_/128), blk>>>(ctx, whi+OFF_O, wlo+OFF_O, b_O,
                                                  out, nullptr, nullptr, MS_, H_, H_);             // 19
}

// round 11
// speedup vs baseline: 2.7399x; 1.0465x over previous
#include <cuda_runtime.h>
#include <cuda_bf16.h>
#include <math.h>

#define B_   2
#define S_   2048
#define H_   2048
#define NH_  16
#define D_   128
#define LAT_ 512
#define MS_  (B_*S_)   // 4096 rows total

// ---------------- scratch (device globals; no allocation allowed) ----------
__device__ float g_ckv[MS_*LAT_];
__device__ float g_cq [MS_*LAT_];
__device__ float g_kr [MS_*D_];
__device__ float g_qr [MS_*D_];
__device__ float g_ctx[MS_*H_];

// pre-split bf16 activations for attention
__device__ __nv_bfloat16 g_khi [MS_*H_], g_klo [MS_*H_];   // K_c  [row][H]
__device__ __nv_bfloat16 g_qhi [MS_*H_], g_qlo [MS_*H_];   // Q_c  [row][H]
__device__ __nv_bfloat16 g_vthi[MS_*H_], g_vtlo[MS_*H_];   // V^T  [H][MS]
__device__ __nv_bfloat16 g_krh [MS_*D_], g_krl [MS_*D_];   // rope(K_r)
__device__ __nv_bfloat16 g_qrh [MS_*D_], g_qrl [MS_*D_];   // rope(Q_r)

// pre-split / transposed bf16 weights ([N][K] layout), hi + lo residual
#define OFF_DKV 0
#define OFF_DQ  1048576
#define OFF_UK  2097152
#define OFF_UV  3145728
#define OFF_UQ  4194304
#define OFF_O   5242880
#define OFF_KR  9437184
#define OFF_QR  9699328
#define WTOT    9961472
__device__ __nv_bfloat16 g_whi[WTOT];
__device__ __nv_bfloat16 g_wlo[WTOT];

// ---------------- weight split + transpose: W[K][N] -> hi/lo [N][K] --------
__global__ void split_transpose(const float* __restrict__ W,
                                __nv_bfloat16* __restrict__ hi,
                                __nv_bfloat16* __restrict__ lo,
                                int K, int N)
{
    __shared__ float tile[32][33];
    const int k0 = blockIdx.y * 32, n0 = blockIdx.x * 32;
    const int tx = threadIdx.x, ty = threadIdx.y;   // 32 x 8
#pragma unroll
    for (int i = ty; i < 32; i += 8)
        tile[i][tx] = W[(k0 + i) * N + n0 + tx];
    __syncthreads();
#pragma unroll
    for (int i = ty; i < 32; i += 8) {
        float v = tile[tx][i];
        __nv_bfloat16 h = __float2bfloat16(v);
        float r = v - __bfloat162float(h);
        hi[(n0 + i) * (long)K + k0 + tx] = h;
        lo[(n0 + i) * (long)K + k0 + tx] = __float2bfloat16(r);
    }
}

// ---------------- split helper: float4 -> packed bf16 hi/lo ----------------
__device__ __forceinline__ void split4(float4 v, uint2& h, uint2& l)
{
    __nv_bfloat162 h0 = __floats2bfloat162_rn(v.x, v.y);
    __nv_bfloat162 h1 = __floats2bfloat162_rn(v.z, v.w);
    float2 f0 = __bfloat1622float2(h0);
    float2 f1 = __bfloat1622float2(h1);
    __nv_bfloat162 l0 = __floats2bfloat162_rn(v.x - f0.x, v.y - f0.y);
    __nv_bfloat162 l1 = __floats2bfloat162_rn(v.z - f1.x, v.w - f1.y);
    h.x = *(unsigned*)&h0; h.y = *(unsigned*)&h1;
    l.x = *(unsigned*)&l0; l.y = *(unsigned*)&l1;
}

__device__ __forceinline__ void mma16816(float* c, const unsigned* a,
                                         unsigned b0, unsigned b1)
{
    asm volatile(
        "mma.sync.aligned.m16n8k16.row.col.f32.bf16.bf16.f32 "
        "{%0,%1,%2,%3}, {%4,%5,%6,%7}, {%8,%9}, {%0,%1,%2,%3};\n"
        : "+f"(c[0]), "+f"(c[1]), "+f"(c[2]), "+f"(c[3])
        : "r"(a[0]), "r"(a[1]), "r"(a[2]), "r"(a[3]), "r"(b0), "r"(b1));
}

// ---------------- bf16-split tensor-core GEMM ------------------------------
// C[M][N] = A[M][K](fp32) @ W(pre-split bf16 [N][K]) + bias, 3-pass hi/lo.
// MODE 0: fp32 C. MODE 1: bf16 hi/lo row-major. MODE 2: bf16 hi/lo transposed
// ([N][MS_] layout, for V^T).
#define GSTRIDE 40
template<int MODE>
__global__ __launch_bounds__(256) void gemm_bf16s(
    const float* __restrict__ A,
    const __nv_bfloat16* __restrict__ Bhi, const __nv_bfloat16* __restrict__ Blo,
    const float* __restrict__ bias, float* __restrict__ C,
    __nv_bfloat16* __restrict__ Chi, __nv_bfloat16* __restrict__ Clo,
    int M, int N, int K)
{
    __shared__ __align__(16) __nv_bfloat16 sm[4][128][GSTRIDE];

    const int tid  = threadIdx.x;
    const int wid  = tid >> 5, lane = tid & 31;
    const int row0 = blockIdx.y * 128, col0 = blockIdx.x * 128;
    const int wm   = (wid >> 1) * 32, wn = (wid & 1) * 64;

    float acc[2][8][4];
#pragma unroll
    for (int t = 0; t < 2; t++)
#pragma unroll
        for (int n = 0; n < 8; n++)
#pragma unroll
            for (int j = 0; j < 4; j++) acc[t][n][j] = 0.f;

    const int a_r = tid >> 1, a_c = (tid & 1) * 16;
    const int b_n = tid >> 1, b_c = (tid & 1) * 16;

    float4 av[4];
    float4 bhv[2], blv[2];

#pragma unroll
    for (int t = 0; t < 4; t++)
        av[t] = *(const float4*)&A[(row0 + a_r) * (long)K + a_c + t * 4];
#pragma unroll
    for (int t = 0; t < 2; t++) {
        bhv[t] = *(const float4*)&Bhi[(col0 + b_n) * (long)K + b_c + t * 8];
        blv[t] = *(const float4*)&Blo[(col0 + b_n) * (long)K + b_c + t * 8];
    }

    for (int k0 = 0; k0 < K; k0 += 32) {
        __syncthreads();
#pragma unroll
        for (int t = 0; t < 4; t++) {
            uint2 h, l;
            split4(av[t], h, l);
            *(uint2*)&sm[0][a_r][a_c + t * 4] = h;
            *(uint2*)&sm[1][a_r][a_c + t * 4] = l;
        }
#pragma unroll
        for (int t = 0; t < 2; t++) {
            *(float4*)&sm[2][b_n][b_c + t * 8] = bhv[t];
            *(float4*)&sm[3][b_n][b_c + t * 8] = blv[t];
        }
        __syncthreads();

        if (k0 + 32 < K) {
#pragma unroll
            for (int t = 0; t < 4; t++)
                av[t] = *(const float4*)&A[(row0 + a_r) * (long)K + k0 + 32 + a_c + t * 4];
#pragma unroll
            for (int t = 0; t < 2; t++) {
                bhv[t] = *(const float4*)&Bhi[(col0 + b_n) * (long)K + k0 + 32 + b_c + t * 8];
                blv[t] = *(const float4*)&Blo[(col0 + b_n) * (long)K + k0 + 32 + b_c + t * 8];
            }
        }

#pragma unroll
        for (int s = 0; s < 2; s++) {
            const int c = s * 16 + (lane & 3) * 2;
            unsigned afh[2][4], afl[2][4];
#pragma unroll
            for (int t = 0; t < 2; t++) {
                int r = wm + t * 16 + (lane >> 2);
                afh[t][0] = *(unsigned*)&sm[0][r][c];
                afh[t][1] = *(unsigned*)&sm[0][r + 8][c];
                afh[t][2] = *(unsigned*)&sm[0][r][c + 8];
                afh[t][3] = *(unsigned*)&sm[0][r + 8][c + 8];
                afl[t][0] = *(unsigned*)&sm[1][r][c];
                afl[t][1] = *(unsigned*)&sm[1][r + 8][c];
                afl[t][2] = *(unsigned*)&sm[1][r][c + 8];
                afl[t][3] = *(unsigned*)&sm[1][r + 8][c + 8];
            }
#pragma unroll
            for (int nt = 0; nt < 8; nt++) {
                int n = wn + nt * 8 + (lane >> 2);
                unsigned bh0 = *(unsigned*)&sm[2][n][c];
                unsigned bh1 = *(unsigned*)&sm[2][n][c + 8];
                unsigned bl0 = *(unsigned*)&sm[3][n][c];
                unsigned bl1 = *(unsigned*)&sm[3][n][c + 8];
#pragma unroll
                for (int t = 0; t < 2; t++) {
                    mma16816(acc[t][nt], afh[t], bh0, bh1);
                    mma16816(acc[t][nt], afh[t], bl0, bl1);
                    mma16816(acc[t][nt], afl[t], bh0, bh1);
                }
            }
        }
    }

#pragma unroll
    for (int t = 0; t < 2; t++) {
        int gr = row0 + wm + t * 16 + (lane >> 2);
#pragma unroll
        for (int nt = 0; nt < 8; nt++) {
            int gc = col0 + wn + nt * 8 + (lane & 3) * 2;
            float2 bv = *(const float2*)&bias[gc];
            float v0 = acc[t][nt][0] + bv.x, v1 = acc[t][nt][1] + bv.y;
            float v2 = acc[t][nt][2] + bv.x, v3 = acc[t][nt][3] + bv.y;
            if (MODE == 0) {
                *(float2*)&C[(long)gr * N + gc]       = make_float2(v0, v1);
                *(float2*)&C[(long)(gr + 8) * N + gc] = make_float2(v2, v3);
            } else if (MODE == 1) {
                __nv_bfloat162 h01 = __floats2bfloat162_rn(v0, v1);
                float2 f01 = __bfloat1622float2(h01);
                __nv_bfloat162 q01 = __floats2bfloat162_rn(v0 - f01.x, v1 - f01.y);
                __nv_bfloat162 h23 = __floats2bfloat162_rn(v2, v3);
                float2 f23 = __bfloat1622float2(h23);
                __nv_bfloat162 q23 = __floats2bfloat162_rn(v2 - f23.x, v3 - f23.y);
                *(__nv_bfloat162*)&Chi[(long)gr * N + gc]       = h01;
                *(__nv_bfloat162*)&Clo[(long)gr * N + gc]       = q01;
                *(__nv_bfloat162*)&Chi[(long)(gr + 8) * N + gc] = h23;
                *(__nv_bfloat162*)&Clo[(long)(gr + 8) * N + gc] = q23;
            } else {
                float vs[4] = {v0, v1, v2, v3};
#pragma unroll
                for (int q = 0; q < 4; q++) {
                    long idx = (long)(gc + (q & 1)) * MS_ + gr + (q >> 1) * 8;
                    __nv_bfloat16 hh = __float2bfloat16(vs[q]);
                    Chi[idx] = hh;
                    Clo[idx] = __float2bfloat16(vs[q] - __bfloat162float(hh));
                }
            }
        }
    }
}

// ---------------- rope: fp32 in -> bf16 hi/lo out --------------------------
__global__ void rope_kernel(const float* __restrict__ x,
                            __nv_bfloat16* __restrict__ oh,
                            __nv_bfloat16* __restrict__ ol)
{
    int row = blockIdx.x;
    int d   = threadIdx.x;
    __shared__ float buf[128];
    buf[d] = x[row * D_ + d];
    __syncthreads();
    int i = d & 63;
    float inv = (float)exp(-(double)(2 * i) / 128.0 * 9.210340371976184);
    float ang = (float)(row & (S_ - 1)) * inv;
    float s, c;
    sincosf(ang, &s, &c);
    float y = (d < 64) ? (buf[d] * c - buf[d + 64] * s)
                       : (buf[d - 64] * s + buf[d] * c);
    __nv_bfloat16 h = __float2bfloat16(y);
    oh[row * D_ + d] = h;
    ol[row * D_ + d] = __float2bfloat16(y - __bfloat162float(h));
}

// ---------------- tensor-core flash attention (bf16 3-pass split) ----------
// grid (S/64, NH, B), 256 threads = 8 warps. Column-split: warp group
// wg=w>>2 handles keys [wg*32, wg*32+32) of each 64-key tile; all groups
// cover all 64 q-rows (warp wr=w&3 owns rows wr*16..wr*16+16). Cross-group
// row max/sum combined through smem each tile; partial PV accumulators
// summed at the end (both groups share identical (m,l) streams).
#define AT_SMEM 191744
__global__ __launch_bounds__(256, 1) void mla_attn_mma(
    const __nv_bfloat16* __restrict__ qhi, const __nv_bfloat16* __restrict__ qlo,
    const __nv_bfloat16* __restrict__ qrh, const __nv_bfloat16* __restrict__ qrl,
    const __nv_bfloat16* __restrict__ khi, const __nv_bfloat16* __restrict__ klo,
    const __nv_bfloat16* __restrict__ krh, const __nv_bfloat16* __restrict__ krl,
    const __nv_bfloat16* __restrict__ vth, const __nv_bfloat16* __restrict__ vtl,
    const int* __restrict__ mask, float* __restrict__ ctx)
{
    extern __shared__ __align__(16) char smx[];
    __nv_bfloat16* QH = (__nv_bfloat16*)smx;
    __nv_bfloat16* QL = QH + 64 * 264;
    __nv_bfloat16* KH = QL + 64 * 264;
    __nv_bfloat16* KL = KH + 64 * 264;
    __nv_bfloat16* VH = KL + 64 * 264;
    __nv_bfloat16* VL = VH + 128 * 72;
    __nv_bfloat16* PH = VL + 128 * 72;
    __nv_bfloat16* PL = PH + 64 * 72;
    float*         MB = (float*)(PL + 64 * 72);
    float*         SMX = MB + 64;     // [2][64] partial row max
    float*         SMS = SMX + 128;   // [2][64] partial row sum

    const int t    = threadIdx.x;
    const int lane = t & 31, w = t >> 5;
    const int wg   = w >> 2, wr = w & 3;
    const int b = blockIdx.z, h = blockIdx.y;
    const int q0 = blockIdx.x * 64;
    const int r0 = wr * 16;
    const int ru = lane >> 2, rv = lane & 3;

    // ---- load Q tile (once); 256 threads: (row, half, quarter) ----
    {
        int r = t & 63, half = (t >> 6) & 1, qq = t >> 7;
        long rowq = (long)(b * S_ + q0 + r);
        const uint4* sH = half ? (const uint4*)&qrh[rowq * D_]
                               : (const uint4*)&qhi[rowq * H_ + h * D_];
        const uint4* sL = half ? (const uint4*)&qrl[rowq * D_]
                               : (const uint4*)&qlo[rowq * H_ + h * D_];
        uint4* dH = (uint4*)(QH + r * 264 + half * 128);
        uint4* dL = (uint4*)(QL + r * 264 + half * 128);
#pragma unroll
        for (int c = qq * 8; c < qq * 8 + 8; c++) { dH[c] = sH[c]; dL[c] = sL[c]; }
    }

    float oacc[16][4];
#pragma unroll
    for (int i = 0; i < 16; i++)
#pragma unroll
        for (int j = 0; j < 4; j++) oacc[i][j] = 0.f;
    float m0 = -1e30f, m1 = -1e30f, l0 = 0.f, l1 = 0.f;
    const float scale = 0.08838834764831845f;   // 1/sqrt(128)

    const unsigned* QHw = (const unsigned*)QH;
    const unsigned* QLw = (const unsigned*)QL;
    const unsigned* KHw = (const unsigned*)KH;
    const unsigned* KLw = (const unsigned*)KL;
    const unsigned* VHw = (const unsigned*)VH;
    const unsigned* VLw = (const unsigned*)VL;
    unsigned* PHw = (unsigned*)PH;
    unsigned* PLw = (unsigned*)PL;

    for (int s0 = 0; s0 < S_; s0 += 64) {
        __syncthreads();
        // ---- K tile ----
        {
            int r = t & 63, half = (t >> 6) & 1, qq = t >> 7;
            long rowk = (long)(b * S_ + s0 + r);
            const uint4* sH = half ? (const uint4*)&krh[rowk * D_]
                                   : (const uint4*)&khi[rowk * H_ + h * D_];
            const uint4* sL = half ? (const uint4*)&krl[rowk * D_]
                                   : (const uint4*)&klo[rowk * H_ + h * D_];
            uint4* dH = (uint4*)(KH + r * 264 + half * 128);
            uint4* dL = (uint4*)(KL + r * 264 + half * 128);
#pragma unroll
            for (int c = qq * 8; c < qq * 8 + 8; c++) { dH[c] = sH[c]; dL[c] = sL[c]; }
        }
        // ---- V^T tile ----
        {
            int row = t >> 1, part = t & 1;
            long vrow = (long)(h * D_ + row);
            const uint4* sH = (const uint4*)&vth[vrow * MS_ + b * S_ + s0];
            const uint4* sL = (const uint4*)&vtl[vrow * MS_ + b * S_ + s0];
            uint4* dH = (uint4*)(VH + row * 72);
            uint4* dL = (uint4*)(VL + row * 72);
#pragma unroll
            for (int c = part * 4; c < part * 4 + 4; c++) { dH[c] = sH[c]; dL[c] = sL[c]; }
        }
        if (t < 64) MB[t] = mask[b * S_ + s0 + t] ? 0.f : -1e30f;
        __syncthreads();

        // ---- QK^T (3-pass), this group's 4 column tiles ----
        float sacc[4][4];
#pragma unroll
        for (int i = 0; i < 4; i++)
#pragma unroll
            for (int j = 0; j < 4; j++) sacc[i][j] = 0.f;
#pragma unroll 1
        for (int ch = 0; ch < 16; ch++) {
            unsigned ah[4], al[4];
            int ab = (r0 + ru) * 132 + ch * 8 + rv;
            ah[0] = QHw[ab];     ah[1] = QHw[ab + 8*132];
            ah[2] = QHw[ab + 4]; ah[3] = QHw[ab + 8*132 + 4];
            al[0] = QLw[ab];     al[1] = QLw[ab + 8*132];
            al[2] = QLw[ab + 4]; al[3] = QLw[ab + 8*132 + 4];
#pragma unroll
            for (int nt = 0; nt < 4; nt++) {
                int gnt = wg * 4 + nt;
                int bb = (gnt * 8 + ru) * 132 + ch * 8 + rv;
                unsigned bh0 = KHw[bb], bh1 = KHw[bb + 4];
                unsigned bl0 = KLw[bb], bl1 = KLw[bb + 4];
                mma16816(sacc[nt], ah, bh0, bh1);
                mma16816(sacc[nt], ah, bl0, bl1);
                mma16816(sacc[nt], al, bh0, bh1);
            }
        }

        // ---- partial row max (this group's 32 keys) ----
        float mx0 = -1e30f, mx1 = -1e30f;
#pragma unroll
        for (int nt = 0; nt < 4; nt++) {
            int col = (wg * 4 + nt) * 8 + rv * 2;
            float mb0 = MB[col], mb1 = MB[col + 1];
            sacc[nt][0] = sacc[nt][0] * scale + mb0;
            sacc[nt][1] = sacc[nt][1] * scale + mb1;
            sacc[nt][2] = sacc[nt][2] * scale + mb0;
            sacc[nt][3] = sacc[nt][3] * scale + mb1;
            mx0 = fmaxf(mx0, fmaxf(sacc[nt][0], sacc[nt][1]));
            mx1 = fmaxf(mx1, fmaxf(sacc[nt][2], sacc[nt][3]));
        }
        mx0 = fmaxf(mx0, __shfl_xor_sync(0xffffffffu, mx0, 1));
        mx0 = fmaxf(mx0, __shfl_xor_sync(0xffffffffu, mx0, 2));
        mx1 = fmaxf(mx1, __shfl_xor_sync(0xffffffffu, mx1, 1));
        mx1 = fmaxf(mx1, __shfl_xor_sync(0xffffffffu, mx1, 2));
        if (rv == 0) {
            SMX[wg * 64 + r0 + ru]     = mx0;
            SMX[wg * 64 + r0 + ru + 8] = mx1;
        }
        __syncthreads();
        float gm0 = fmaxf(SMX[r0 + ru],     SMX[64 + r0 + ru]);
        float gm1 = fmaxf(SMX[r0 + ru + 8], SMX[64 + r0 + ru + 8]);
        float mn0 = fmaxf(m0, gm0), mn1 = fmaxf(m1, gm1);
        float cr0 = __expf(m0 - mn0), cr1 = __expf(m1 - mn1);
        m0 = mn0; m1 = mn1;
#pragma unroll
        for (int nt = 0; nt < 16; nt++) {
            oacc[nt][0] *= cr0; oacc[nt][1] *= cr0;
            oacc[nt][2] *= cr1; oacc[nt][3] *= cr1;
        }
        float rs0 = 0.f, rs1 = 0.f;
#pragma unroll
        for (int nt = 0; nt < 4; nt++) {
            float p0 = __expf(sacc[nt][0] - mn0), p1 = __expf(sacc[nt][1] - mn0);
            float p2 = __expf(sacc[nt][2] - mn1), p3 = __expf(sacc[nt][3] - mn1);
            rs0 += p0 + p1; rs1 += p2 + p3;
            __nv_bfloat162 h01 = __floats2bfloat162_rn(p0, p1);
            float2 f01 = __bfloat1622float2(h01);
            __nv_bfloat162 q01 = __floats2bfloat162_rn(p0 - f01.x, p1 - f01.y);
            __nv_bfloat162 h23 = __floats2bfloat162_rn(p2, p3);
            float2 f23 = __bfloat1622float2(h23);
            __nv_bfloat162 q23 = __floats2bfloat162_rn(p2 - f23.x, p3 - f23.y);
            int gnt = wg * 4 + nt;
            int w0 = (r0 + ru) * 36 + gnt * 4 + rv;
            int w1 = (r0 + ru + 8) * 36 + gnt * 4 + rv;
            PHw[w0] = *(unsigned*)&h01; PLw[w0] = *(unsigned*)&q01;
            PHw[w1] = *(unsigned*)&h23; PLw[w1] = *(unsigned*)&q23;
        }
        rs0 += __shfl_xor_sync(0xffffffffu, rs0, 1);
        rs0 += __shfl_xor_sync(0xffffffffu, rs0, 2);
        rs1 += __shfl_xor_sync(0xffffffffu, rs1, 1);
        rs1 += __shfl_xor_sync(0xffffffffu, rs1, 2);
        if (rv == 0) {
            SMS[wg * 64 + r0 + ru]     = rs0;
            SMS[wg * 64 + r0 + ru + 8] = rs1;
        }
        __syncthreads();   // P + sums complete
        l0 = l0 * cr0 + SMS[r0 + ru]     + SMS[64 + r0 + ru];
        l1 = l1 * cr1 + SMS[r0 + ru + 8] + SMS[64 + r0 + ru + 8];

        // ---- P @ V (3-pass), this group's 32 keys = 2 k-chunks ----
#pragma unroll 1
        for (int chl = 0; chl < 2; chl++) {
            int ch = wg * 2 + chl;
            unsigned ph[4], pl[4];
            int ab = (r0 + ru) * 36 + ch * 8 + rv;
            ph[0] = PHw[ab];     ph[1] = PHw[ab + 8*36];
            ph[2] = PHw[ab + 4]; ph[3] = PHw[ab + 8*36 + 4];
            pl[0] = PLw[ab];     pl[1] = PLw[ab + 8*36];
            pl[2] = PLw[ab + 4]; pl[3] = PLw[ab + 8*36 + 4];
#pragma unroll
            for (int nt = 0; nt < 16; nt++) {
                int bb = (nt * 8 + ru) * 36 + ch * 8 + rv;
                unsigned vh0 = VHw[bb], vh1 = VHw[bb + 4];
                unsigned vl0 = VLw[bb], vl1 = VLw[bb + 4];
                mma16816(oacc[nt], ph, vh0, vh1);
                mma16816(oacc[nt], ph, vl0, vl1);
                mma16816(oacc[nt], pl, vh0, vh1);
            }
        }
    }

    // ---- combine the two groups' partial PV sums (reuse KH region) ----
    __syncthreads();
    float* OC = (float*)KH;   // 64 rows x 132 stride fp32 = 33,792 B
    if (wg == 1) {
#pragma unroll
        for (int nt = 0; nt < 16; nt++) {
            int d0 = nt * 8 + rv * 2;
            *(float2*)&OC[(r0 + ru) * 132 + d0] =
                make_float2(oacc[nt][0], oacc[nt][1]);
            *(float2*)&OC[(r0 + ru + 8) * 132 + d0] =
                make_float2(oacc[nt][2], oacc[nt][3]);
        }
    }
    __syncthreads();
    if (wg == 0) {
        float inv0 = 1.f / l0, inv1 = 1.f / l1;
        long row0 = (long)(b * S_ + q0 + r0 + ru);
#pragma unroll
        for (int nt = 0; nt < 16; nt++) {
            int d0 = nt * 8 + rv * 2;
            float2 pB0 = *(float2*)&OC[(r0 + ru) * 132 + d0];
            float2 pB1 = *(float2*)&OC[(r0 + ru + 8) * 132 + d0];
            *(float2*)&ctx[row0 * H_ + h * D_ + d0] =
                make_float2((oacc[nt][0] + pB0.x) * inv0,
                            (oacc[nt][1] + pB0.y) * inv0);
            *(float2*)&ctx[(row0 + 8) * H_ + h * D_ + d0] =
                make_float2((oacc[nt][2] + pB1.x) * inv1,
                            (oacc[nt][3] + pB1.y) * inv1);
        }
    }
}

// ---------------- launch ----------------------------------------------------
extern "C" void kernel_launch(void* const* d_in, const int* in_sizes, int n_in,
                              void* d_out, int out_size)
{
    const float* hs    = (const float*)d_in[0];
    const int*   mask  = (const int*)  d_in[1];
    const float* W_DKV = (const float*)d_in[2];  const float* b_DKV = (const float*)d_in[3];
    const float* W_DQ  = (const float*)d_in[4];  const float* b_DQ  = (const float*)d_in[5];
    const float* W_UK  = (const float*)d_in[6];  const float* b_UK  = (const float*)d_in[7];
    const float* W_UV  = (const float*)d_in[8];  const float* b_UV  = (const float*)d_in[9];
    const float* W_UQ  = (const float*)d_in[10]; const float* b_UQ  = (const float*)d_in[11];
    const float* W_KR  = (const float*)d_in[12]; const float* b_KR  = (const float*)d_in[13];
    const float* W_QR  = (const float*)d_in[14]; const float* b_QR  = (const float*)d_in[15];
    const float* W_O   = (const float*)d_in[16]; const float* b_O   = (const float*)d_in[17];
    float* out = (float*)d_out;

    float *ckv, *cq, *kr, *qr, *ctx;
    __nv_bfloat16 *whi, *wlo;
    __nv_bfloat16 *khi, *klo, *qhi, *qlo, *vthi, *vtlo, *krh, *krl, *qrh, *qrl;
    cudaGetSymbolAddress((void**)&ckv,  g_ckv);
    cudaGetSymbolAddress((void**)&cq,   g_cq);
    cudaGetSymbolAddress((void**)&kr,   g_kr);
    cudaGetSymbolAddress((void**)&qr,   g_qr);
    cudaGetSymbolAddress((void**)&ctx,  g_ctx);
    cudaGetSymbolAddress((void**)&whi,  g_whi);
    cudaGetSymbolAddress((void**)&wlo,  g_wlo);
    cudaGetSymbolAddress((void**)&khi,  g_khi);
    cudaGetSymbolAddress((void**)&klo,  g_klo);
    cudaGetSymbolAddress((void**)&qhi,  g_qhi);
    cudaGetSymbolAddress((void**)&qlo,  g_qlo);
    cudaGetSymbolAddress((void**)&vthi, g_vthi);
    cudaGetSymbolAddress((void**)&vtlo, g_vtlo);
    cudaGetSymbolAddress((void**)&krh,  g_krh);
    cudaGetSymbolAddress((void**)&krl,  g_krl);
    cudaGetSymbolAddress((void**)&qrh,  g_qrh);
    cudaGetSymbolAddress((void**)&qrl,  g_qrl);

    cudaFuncSetAttribute(mla_attn_mma,
                         cudaFuncAttributeMaxDynamicSharedMemorySize, AT_SMEM);

    const dim3 blk(256);
    const dim3 tblk(32, 8);

    split_transpose<<<dim3(LAT_/32, H_/32),  tblk>>>(W_DKV, whi+OFF_DKV, wlo+OFF_DKV, H_,  LAT_); // 1
    split_transpose<<<dim3(H_/32,  LAT_/32), tblk>>>(W_UK,  whi+OFF_UK,  wlo+OFF_UK,  LAT_, H_);  // 2
    split_transpose<<<dim3(H_/32,  LAT_/32), tblk>>>(W_UV,  whi+OFF_UV,  wlo+OFF_UV,  LAT_, H_);  // 3
    gemm_bf16s<0><<<dim3(LAT_/128, MS_/128), blk>>>(hs, whi+OFF_DKV, wlo+OFF_DKV, b_DKV,
                                                    ckv, nullptr, nullptr, MS_, LAT_, H_);         // 4
    split_transpose<<<dim3(H_/32,  LAT_/32), tblk>>>(W_UQ,  whi+OFF_UQ,  wlo+OFF_UQ,  LAT_, H_);  // 5
    gemm_bf16s<1><<<dim3(H_/128, MS_/128), blk>>>(ckv, whi+OFF_UK, wlo+OFF_UK, b_UK,
                                                  nullptr, khi, klo, MS_, H_, LAT_);               // 6 (profiled)
    gemm_bf16s<2><<<dim3(H_/128, MS_/128), blk>>>(ckv, whi+OFF_UV, wlo+OFF_UV, b_UV,
                                                  nullptr, vthi, vtlo, MS_, H_, LAT_);             // 7
    split_transpose<<<dim3(LAT_/32, H_/32),  tblk>>>(W_DQ, whi+OFF_DQ, wlo+OFF_DQ, H_, LAT_);     // 8
    gemm_bf16s<0><<<dim3(LAT_/128, MS_/128), blk>>>(hs, whi+OFF_DQ, wlo+OFF_DQ, b_DQ,
                                                    cq, nullptr, nullptr, MS_, LAT_, H_);          // 9
    gemm_bf16s<1><<<dim3(H_/128, MS_/128), blk>>>(cq, whi+OFF_UQ, wlo+OFF_UQ, b_UQ,
                                                  nullptr, qhi, qlo, MS_, H_, LAT_);               // 10
    split_transpose<<<dim3(D_/32, H_/32), tblk>>>(W_KR, whi+OFF_KR, wlo+OFF_KR, H_, D_);          // 11
    gemm_bf16s<0><<<dim3(1, MS_/128), blk>>>(hs, whi+OFF_KR, wlo+OFF_KR, b_KR,
                                             kr, nullptr, nullptr, MS_, D_, H_);                   // 12
    split_transpose<<<dim3(D_/32, H_/32), tblk>>>(W_QR, whi+OFF_QR, wlo+OFF_QR, H_, D_);          // 13
    gemm_bf16s<0><<<dim3(1, MS_/128), blk>>>(hs, whi+OFF_QR, wlo+OFF_QR, b_QR,
                                             qr, nullptr, nullptr, MS_, D_, H_);                   // 14
    rope_kernel<<<MS_, 128>>>(kr, krh, krl);                                                       // 15
    rope_kernel<<<MS_, 128>>>(qr, qrh, qrl);                                                       // 16
    split_transpose<<<dim3(H_/32, H_/32), tblk>>>(W_O, whi+OFF_O, wlo+OFF_O, H_, H_);             // 17

    mla_attn_mma<<<dim3(S_/64, NH_, B_), 256, AT_SMEM>>>(
        qhi, qlo, qrh, qrl, khi, klo, krh, krl, vthi, vtlo, mask, ctx);                            // 18

    gemm_bf16s<0><<<dim3(H_/128, MS_/128), blk>>>(ctx, whi+OFF_O, wlo+OFF_O, b_O,
                                                  out, nullptr, nullptr, MS_, H_, H_);             // 19
}